// round 17
// baseline (speedup 1.0000x reference)
#include <cuda_runtime.h>
#include <math.h>

#define FULL 0xFFFFFFFFu
#define T_LEN 2048
#define NROWS 8192
#define WPB 8              // warps/block; 8 independent quarter-row units per block

// persistent scratch (zero-init at load; counters reset by each finalizer)
__device__ float2   g_part[NROWS * 4];   // (sumt, sumidx) per (row, quarter)
__device__ float2   g_extra[NROWS];      // (S, T) from q0
__device__ unsigned g_cnt[NROWS];        // arrival counters (0 at rest)

// streaming sums for one chunk (absolute element base = abase)
#define SUMS(e, m, abase)                                                 \
    do {                                                                  \
        sumt = fmaf((m).x, (e).x, sumt); sumt = fmaf((m).y, (e).y, sumt); \
        sumt = fmaf((m).z, (e).z, sumt); sumt = fmaf((m).w, (e).w, sumt); \
        const float cnt_ = ((m).x + (m).y) + ((m).z + (m).w);             \
        sumidx = fmaf(cnt_, (float)(abase), sumidx);                      \
        sumidx += fmaf(3.f, (m).w, fmaf(2.f, (m).z, (m).y));              \
    } while (0)

// gated scan + exp for one chunk; updates S, T (warp-uniform gate)
#define P1CHUNK(e, m)                                                     \
    do {                                                                  \
        if (beta * T < 106.f) {                                           \
            const float cnt = ((m).x + (m).y) + ((m).z + (m).w);          \
            float s = cnt;                                                \
            _Pragma("unroll")                                             \
            for (int off = 1; off < 32; off <<= 1) {                      \
                const float u = __shfl_up_sync(FULL, s, off);             \
                if (lane >= off) s += u;                                  \
            }                                                             \
            if (beta * T < 104.f) {                                       \
                float k = T + (s - cnt);                                  \
                if ((m).x > 0.5f) { S += expf(fmaf(mu, (e).x, -beta * k)); k += 1.f; } \
                if ((m).y > 0.5f) { S += expf(fmaf(mu, (e).y, -beta * k)); k += 1.f; } \
                if ((m).z > 0.5f) { S += expf(fmaf(mu, (e).z, -beta * k)); k += 1.f; } \
                if ((m).w > 0.5f) { S += expf(fmaf(mu, (e).w, -beta * k)); } \
            }                                                             \
            T += __shfl_sync(FULL, s, 31);                                \
        }                                                                 \
    } while (0)

__global__ __launch_bounds__(256, 4)
void scpp_kernel(const float* __restrict__ event_times,
                 const float* __restrict__ input_mask,
                 const float* __restrict__ t0p,
                 const float* __restrict__ t1p,
                 const float* __restrict__ mup,
                 const float* __restrict__ betap,
                 float* __restrict__ out)
{
    const int lane = threadIdx.x & 31;
    const int w    = threadIdx.x >> 5;
    const int unit = blockIdx.x * WPB + w;
    const int row  = unit >> 2;
    const int q    = unit & 3;

    const float4* evr = reinterpret_cast<const float4*>(event_times + (size_t)row * T_LEN);
    const float4* mkr = reinterpret_cast<const float4*>(input_mask  + (size_t)row * T_LEN);

    float sumt = 0.f, sumidx = 0.f, S = 0.f, T = 0.f;

    if (q == 0) {
        // ---- chunks 0..2 + all scan/exp duty ----
        const float4 e0 = evr[lane +  0], e1 = evr[lane + 32], e2 = evr[lane + 64];
        const float4 m0 = mkr[lane +  0], m1 = mkr[lane + 32], m2 = mkr[lane + 64];

        const float mu   = log1pf(expf(__ldg(mup)));
        const float beta = log1pf(expf(__ldg(betap)));

        const int ab = 4 * lane;
        SUMS(e0, m0, ab +   0);
        SUMS(e1, m1, ab + 128);
        SUMS(e2, m2, ab + 256);

        P1CHUNK(e0, m0);
        P1CHUNK(e1, m1);
        P1CHUNK(e2, m2);
        // rare fallback (arbitrary masks): continue scan+exp over chunks 3..15
        if (beta * T < 106.f) {
            for (int i = 3; i < 16 && beta * T < 106.f; i++) {
                const float4 e = evr[lane + 32 * i];
                const float4 m = mkr[lane + 32 * i];
                P1CHUNK(e, m);
            }
        }
    } else if (q == 1) {
        // ---- chunks 3..6 ----
        const float4 e0 = evr[lane + 32*3], e1 = evr[lane + 32*4];
        const float4 e2 = evr[lane + 32*5], e3 = evr[lane + 32*6];
        const float4 m0 = mkr[lane + 32*3], m1 = mkr[lane + 32*4];
        const float4 m2 = mkr[lane + 32*5], m3 = mkr[lane + 32*6];
        const int ab = 4 * lane;
        SUMS(e0, m0, ab + 384); SUMS(e1, m1, ab + 512);
        SUMS(e2, m2, ab + 640); SUMS(e3, m3, ab + 768);
    } else if (q == 2) {
        // ---- chunks 7..10 ----
        const float4 e0 = evr[lane + 32*7], e1 = evr[lane + 32*8];
        const float4 e2 = evr[lane + 32*9], e3 = evr[lane + 32*10];
        const float4 m0 = mkr[lane + 32*7], m1 = mkr[lane + 32*8];
        const float4 m2 = mkr[lane + 32*9], m3 = mkr[lane + 32*10];
        const int ab = 4 * lane;
        SUMS(e0, m0, ab +  896); SUMS(e1, m1, ab + 1024);
        SUMS(e2, m2, ab + 1152); SUMS(e3, m3, ab + 1280);
    } else {
        // ---- chunks 11..15 ----
        const float4 e0 = evr[lane + 32*11], e1 = evr[lane + 32*12];
        const float4 e2 = evr[lane + 32*13], e3 = evr[lane + 32*14];
        const float4 e4 = evr[lane + 32*15];
        const float4 m0 = mkr[lane + 32*11], m1 = mkr[lane + 32*12];
        const float4 m2 = mkr[lane + 32*13], m3 = mkr[lane + 32*14];
        const float4 m4 = mkr[lane + 32*15];
        const int ab = 4 * lane;
        SUMS(e0, m0, ab + 1408); SUMS(e1, m1, ab + 1536);
        SUMS(e2, m2, ab + 1664); SUMS(e3, m3, ab + 1792);
        SUMS(e4, m4, ab + 1920);
    }

    // ---- warp reductions ----
    #pragma unroll
    for (int off = 16; off; off >>= 1) {
        sumt   += __shfl_down_sync(FULL, sumt,   off);
        sumidx += __shfl_down_sync(FULL, sumidx, off);
        S      += __shfl_down_sync(FULL, S,      off);
    }

    // ---- publish partial; last-arriving warp finalizes (threadFenceReduction pattern) ----
    if (lane == 0) {
        g_part[(row << 2) | q] = make_float2(sumt, sumidx);
        if (q == 0) g_extra[row] = make_float2(S, T);
        __threadfence();                         // release: partials visible before count
        const unsigned old = atomicAdd(&g_cnt[row], 1u);
        if (old == 3u) {
            __threadfence();                     // acquire: observe all 4 partials
            const float2 p0 = g_part[(row << 2) | 0];
            const float2 p1 = g_part[(row << 2) | 1];
            const float2 p2 = g_part[(row << 2) | 2];
            const float2 p3 = g_part[(row << 2) | 3];
            const float2 ex = g_extra[row];

            const float mu   = log1pf(expf(__ldg(mup)));
            const float beta = log1pf(expf(__ldg(betap)));
            const float t0   = __ldg(t0p);
            const float t1   = __ldg(t1p);

            const float st = (p0.x + p1.x) + (p2.x + p3.x);
            const float si = (p0.y + p1.y) + (p2.y + p3.y);

            const float ll  = fmaf(mu, st, -beta * si);
            const float emb = expf(-beta);
            // telescoped compensator: (1-e^{-b})*S - e^{mu*t0} + e^{mu*t1 - b*M}
            float comp = fmaf(1.f - emb, ex.x, -expf(mu * t0));
            comp += expf(fmaf(mu, t1, -beta * ex.y));   // exact 0 after underflow
            out[row] = ll - comp / mu;

            g_cnt[row] = 0;                      // reset for next graph replay
        }
    }
}

extern "C" void kernel_launch(void* const* d_in, const int* in_sizes, int n_in,
                              void* d_out, int out_size)
{
    const float* event_times = (const float*)d_in[0];
    // d_in[1] = spatial_locations : unused by the op
    const float* input_mask  = (const float*)d_in[2];
    const float* t0          = (const float*)d_in[3];
    const float* t1          = (const float*)d_in[4];
    const float* mu_param    = (const float*)d_in[5];
    const float* beta_param  = (const float*)d_in[6];
    float* out = (float*)d_out;

    const int n_units  = NROWS * 4;            // 32768 quarter-row units
    const int n_blocks = n_units / WPB;        // 4096
    scpp_kernel<<<n_blocks, 256>>>(event_times, input_mask,
                                   t0, t1, mu_param, beta_param, out);
}